// round 10
// baseline (speedup 1.0000x reference)
#include <cuda_runtime.h>
#include <cstdint>

#define NN 10000
#define NE 80000

__device__ float g_xn  [NN*576];
__device__ float g_rad [NE*384];
__device__ float g_val0[NE*128];
__device__ float g_gdir[NE*256];
__device__ float g_gten[NE*256];
__device__ float g_e   [NE*8];
__device__ float g_xjp [NN*1024];
__device__ float g_num [NN*1152];
__device__ float g_den [NN*8];
__device__ float g_x1  [NN*576];
__device__ float g_yn  [NN*576];
__device__ float g_h   [NN*1024];
__device__ float g_gsil[NN*128];
__device__ float g_gsig[NN*128];

// pre-converted tf32 weights in FRAGMENT-INTERLEAVED SMEM-image layout:
// within a 128x128 chunk (QS=264): pos = kk*4*QS + q*QS + 2n + h, k = kk*8 + h*4 + q
// 128x64 chunks use QS=136. Staging to SMEM is a pure linear copy.
__device__ __align__(16) uint32_t g_W1c [16896];
__device__ __align__(16) uint32_t g_W2c [50688];
__device__ __align__(16) uint32_t g_Wm0c[118272];
__device__ __align__(16) uint32_t g_Wc1c[50688];
__device__ __align__(16) uint32_t g_Wc2c[50688];
__device__ __align__(16) uint32_t g_Wpc [26112];
__device__ __align__(16) uint32_t g_Wf1c[25344];
__device__ __align__(16) uint32_t g_Wf2c[26112];
__device__ __align__(16) uint32_t g_Wxjc[8448];
__device__ __align__(16) uint32_t g_Wgc [8448];

__device__ __forceinline__ float sigm(float z) { return 1.f / (1.f + __expf(-z)); }

__device__ __forceinline__ uint32_t f2tf(float x) {
    uint32_t r; asm("cvt.rna.tf32.f32 %0, %1;" : "=r"(r) : "f"(x)); return r;
}
__device__ __forceinline__ void red2(float* p, float a, float b) {
    asm volatile("red.global.add.v2.f32 [%0], {%1,%2};" :: "l"(p), "f"(a), "f"(b) : "memory");
}
__device__ __forceinline__ void mma8(float* d, uint32_t a0,uint32_t a1,uint32_t a2,uint32_t a3,
                                     uint32_t b0,uint32_t b1) {
    asm volatile("mma.sync.aligned.m16n8k8.row.col.f32.tf32.tf32.f32 "
                 "{%0,%1,%2,%3},{%4,%5,%6,%7},{%8,%9},{%0,%1,%2,%3};"
                 : "+f"(d[0]),"+f"(d[1]),"+f"(d[2]),"+f"(d[3])
                 : "r"(a0),"r"(a1),"r"(a2),"r"(a3),"r"(b0),"r"(b1));
}

__device__ __forceinline__ int pairpos(int k, int n, int QS) {
    return (k>>3)*4*QS + (k&3)*QS + n*2 + ((k>>2)&1);
}

// Warp tile 32 rows x 32 cols. XST = Xs row stride; QS = Ws per-q stride; NK = k-steps.
template<int XST, int QS, int NK>
__device__ __forceinline__ void gemm_mma(const uint32_t* __restrict__ Ws,
                                         const uint32_t* __restrict__ Xs,
                                         int lane, int mg, int ng, float acc[8][4])
{
    const uint32_t* xb = Xs + (mg*32 + (lane>>2))*XST + (lane&3);
    const uint32_t* wb = Ws + (lane&3)*QS + (ng*32 + (lane>>2))*2;
#pragma unroll 4
    for (int kk = 0; kk < NK; kk++) {
        const uint32_t* xp = xb + kk*8;
        uint32_t a00 = xp[0],      a01 = xp[8*XST],   a02 = xp[4],        a03 = xp[8*XST+4];
        uint32_t a10 = xp[16*XST], a11 = xp[24*XST],  a12 = xp[16*XST+4], a13 = xp[24*XST+4];
        const uint32_t* wp = wb + kk*4*QS;
        uint2 b[4];
#pragma unroll
        for (int nt = 0; nt < 4; nt++) b[nt] = *(const uint2*)(wp + nt*16);
#pragma unroll
        for (int nt = 0; nt < 4; nt++) {
            mma8(acc[nt],   a00,a01,a02,a03, b[nt].x, b[nt].y);
            mma8(acc[4+nt], a10,a11,a12,a13, b[nt].x, b[nt].y);
        }
    }
}

// ---------------- weight pre-conversion into fragment layout ----------------
__global__ void __launch_bounds__(256) wconv_kernel(
    const float* __restrict__ W1, const float* __restrict__ W2,
    const float* __restrict__ Wm0, const float* __restrict__ Wc1,
    const float* __restrict__ Wc2, const float* __restrict__ Wp,
    const float* __restrict__ Wf1, const float* __restrict__ Wf2,
    const float* __restrict__ Wxj, const float* __restrict__ Wg)
{
    int i = blockIdx.x*256 + threadIdx.x;
    if (i < 16384) { int k=i>>7, n=i&127;
        g_W1c[pairpos(k,n,264)] = f2tf(W1[i]); return; } i -= 16384;
    if (i < 49152) { int j=i/16384, r=i&16383, k=r>>7, n=r&127;
        g_W2c[j*16896 + pairpos(k,n,264)] = f2tf(W2[k*384 + j*128 + n]); return; } i -= 49152;
    if (i < 114688){ int j=i/16384, r=i&16383, k=r>>7, n=r&127;
        g_Wm0c[j*16896 + pairpos(k,n,264)] = f2tf(Wm0[k*896 + j*128 + n]); return; } i -= 114688;
    if (i < 49152) { int d=i>>14, r=i&16383, k=r>>7, n=r&127;
        g_Wc1c[d*16896 + pairpos(k,n,264)] = f2tf(Wc1[i]); return; } i -= 49152;
    if (i < 49152) { int d=i>>14, r=i&16383, k=r>>7, n=r&127;
        g_Wc2c[d*16896 + pairpos(k,n,264)] = f2tf(Wc2[i]); return; } i -= 49152;
    if (i < 24576) { int d=i>>13, r=i&8191, k=r>>6, n=r&63;
        g_Wpc[d*8704 + pairpos(k,n,136)] = f2tf(Wp[i]); return; } i -= 24576;
    if (i < 16384) { int d=(i>>13)+1, r=i&8191, k=r>>7, n=r&127;
        g_Wf1c[d*8448 + pairpos(k,n,264)] = f2tf(Wf1[d*8192 + r]); return; } i -= 16384;
    if (i < 24576) { int d=i>>13, r=i&8191, k=r>>6, n=r&63;
        g_Wf2c[d*8704 + pairpos(k,n,136)] = f2tf(Wf2[i]); return; } i -= 24576;
    if (i < 8192)  { int k=i>>7, n=i&127;
        g_Wxjc[pairpos(k,n,264)] = f2tf(Wxj[i]); return; } i -= 8192;
    if (i < 8192)  { int k=i>>7, n=i&127;
        g_Wgc[pairpos(k,n,264)] = f2tf(Wg[i]); return; }
}
#define WCONV_N 360448

__global__ void zero_kernel() {
    size_t i = (size_t)blockIdx.x * blockDim.x + threadIdx.x;
    if (i < NN*1152/4) ((float4*)g_num)[i] = make_float4(0.f,0.f,0.f,0.f);
    if (i < NN*8)      g_den[i] = 0.f;
}

// ---------------- enorm: 4 nodes / 256-thread block ----------------
__global__ void __launch_bounds__(256) enorm_kernel(const float* __restrict__ src, float* __restrict__ dst) {
    int n = blockIdx.x*4 + (threadIdx.x >> 6);
    int c = threadIdx.x & 63;
    const float* p = src + (size_t)n*576 + c;
    float v[9];
#pragma unroll
    for (int k = 0; k < 9; k++) v[k] = p[k*64];
    float s0 = v[0]*v[0];
    float s1 = v[1]*v[1] + v[2]*v[2] + v[3]*v[3];
    float s2 = v[4]*v[4] + v[5]*v[5] + v[6]*v[6] + v[7]*v[7] + v[8]*v[8];
#pragma unroll
    for (int off = 16; off; off >>= 1) {
        s0 += __shfl_xor_sync(0xffffffffu, s0, off);
        s1 += __shfl_xor_sync(0xffffffffu, s1, off);
        s2 += __shfl_xor_sync(0xffffffffu, s2, off);
    }
    __shared__ float red[4][3][2];
    int g = threadIdx.x >> 6, hw = (c >> 5);
    if ((c & 31) == 0) { red[g][0][hw] = s0; red[g][1][hw] = s1; red[g][2][hw] = s2; }
    __syncthreads();
    float sc0 = rsqrtf((red[g][0][0]+red[g][0][1]) * (1.f/64.f)  + 1e-6f);
    float sc1 = rsqrtf((red[g][1][0]+red[g][1][1]) * (1.f/192.f) + 1e-6f);
    float sc2 = rsqrtf((red[g][2][0]+red[g][2][1]) * (1.f/320.f) + 1e-6f);
    float* q = dst + (size_t)n*576 + c;
    q[0] = v[0]*sc0;
#pragma unroll
    for (int k = 1; k < 4; k++) q[k*64] = v[k]*sc1;
#pragma unroll
    for (int k = 4; k < 9; k++) q[k*64] = v[k]*sc2;
}

// linear SMEM staging (weights are pre-laid-out)
template<int NW4, int NT>
__device__ __forceinline__ void stage_copy(uint32_t* Ws, const uint32_t* __restrict__ src, int t) {
    const uint4* s4 = (const uint4*)src;
    uint4* d4 = (uint4*)Ws;
    for (int i = t; i < NW4; i += NT) d4[i] = s4[i];
}

// ---------------- xjp: 80000 rows x 128, K=64 ----------------
#define XJ_GRID 1250
__global__ void __launch_bounds__(256) xjp_mma()
{
    extern __shared__ uint32_t sm[];
    uint32_t* Xs = sm;            // 64*68 = 4352
    uint32_t* Ws = sm + 4352;     // 8448
    int rbase = blockIdx.x * 64;
    int t = threadIdx.x, lane = t & 31, w = t >> 5, mg = w & 1, ng = w >> 1;
    stage_copy<2112,256>(Ws, g_Wxjc, t);
    {
        int r = t >> 2, q = t & 3;
        int gr = rbase + r;
        int node = gr >> 3, slot = 1 + (gr & 7);
        const float4* yp = (const float4*)&g_xn[(size_t)node*576 + slot*64 + q*16];
        uint32_t* col = Xs + r*68 + q*16;
#pragma unroll
        for (int i = 0; i < 4; i++) {
            float4 v = yp[i];
            *(uint4*)(col + i*4) = make_uint4(f2tf(v.x), f2tf(v.y), f2tf(v.z), f2tf(v.w));
        }
    }
    __syncthreads();
    float acc[8][4] = {};
    gemm_mma<68,264,8>(Ws, Xs, lane, mg, ng, acc);
    int nbase = ng*32 + (lane&3)*2;
    int ebase = mg*32 + (lane>>2);
#pragma unroll
    for (int mt = 0; mt < 2; mt++)
#pragma unroll
    for (int hf = 0; hf < 2; hf++) {
        int gr = rbase + ebase + mt*16 + hf*8;
        int node = gr >> 3, slot = gr & 7;
        size_t ob = (size_t)node*1024 + (size_t)slot*128;
#pragma unroll
        for (int nt = 0; nt < 4; nt++) {
            int n = nbase + nt*8;
            *(float2*)&g_xjp[ob + n] =
                make_float2(acc[mt*4+nt][hf*2+0], acc[mt*4+nt][hf*2+1]);
        }
    }
}

// ---------------- gate: 10000 rows x 128, K=64 ----------------
#define GATE_GRID 157
__global__ void __launch_bounds__(256) gate_mma(const float* __restrict__ bg)
{
    extern __shared__ uint32_t sm[];
    uint32_t* Xs = sm;
    uint32_t* Ws = sm + 4352;
    int rbase = blockIdx.x * 64;
    int t = threadIdx.x, lane = t & 31, w = t >> 5, mg = w & 1, ng = w >> 1;
    stage_copy<2112,256>(Ws, g_Wgc, t);
    {
        int r = t >> 2, q = t & 3;
        int node = rbase + r;
        uint32_t* col = Xs + r*68 + q*16;
        if (node < NN) {
            const float4* yp = (const float4*)&g_yn[(size_t)node*576 + q*16];
#pragma unroll
            for (int i = 0; i < 4; i++) {
                float4 v = yp[i];
                *(uint4*)(col + i*4) = make_uint4(f2tf(v.x), f2tf(v.y), f2tf(v.z), f2tf(v.w));
            }
        } else {
#pragma unroll
            for (int i = 0; i < 4; i++) *(uint4*)(col + i*4) = make_uint4(0,0,0,0);
        }
    }
    __syncthreads();
    float acc[8][4] = {};
    gemm_mma<68,264,8>(Ws, Xs, lane, mg, ng, acc);
    int nbase = ng*32 + (lane&3)*2;
    int ebase = mg*32 + (lane>>2);
#pragma unroll
    for (int mt = 0; mt < 2; mt++)
#pragma unroll
    for (int hf = 0; hf < 2; hf++) {
        int node = rbase + ebase + mt*16 + hf*8;
        if (node >= NN) continue;
        size_t ob = (size_t)node*128;
#pragma unroll
        for (int nt = 0; nt < 4; nt++) {
            int n = nbase + nt*8;
            float z0 = acc[mt*4+nt][hf*2+0] + bg[n];
            float z1 = acc[mt*4+nt][hf*2+1] + bg[n+1];
            float s0 = sigm(z0), s1 = sigm(z1);
            *(float2*)&g_gsil[ob + n] = make_float2(z0*s0, z1*s1);
            *(float2*)&g_gsig[ob + n] = make_float2(s0, s1);
        }
    }
}

// ---------------- radial MLP: 128 edges/block ----------------
__global__ void __launch_bounds__(512,2) rad_kernel(
    const float* __restrict__ edist, const float* __restrict__ semb,
    const float* __restrict__ temb,  const float* __restrict__ b1,
    const float* __restrict__ b2,    const int* __restrict__ anum,
    const int* __restrict__ eidx)
{
    extern __shared__ uint32_t sm[];
    uint32_t* ef = sm;            // 16896
    uint32_t* Ws = sm + 16896;    // 8448
    int* zsrc = (int*)(sm + 25344);
    int* ztgt = zsrc + 128;
    int e0 = blockIdx.x * 128, t = threadIdx.x;
    int lane = t & 31, w = t >> 5, mg = w & 3, ng = w >> 2;
    if (t < 128)      zsrc[t]     = anum[eidx[e0 + t]];
    else if (t < 256) ztgt[t-128] = anum[eidx[NE + e0 + t - 128]];
    __syncthreads();
    {
        int e = t >> 2, q = t & 3;
        const float4* xp;
        if (q < 2)      xp = (const float4*)&edist[(size_t)(e0+e)*64 + q*32];
        else if (q==2)  xp = (const float4*)&semb[(size_t)zsrc[e]*32];
        else            xp = (const float4*)&temb[(size_t)ztgt[e]*32];
        uint32_t* col = ef + e*132 + q*32;
#pragma unroll
        for (int i4 = 0; i4 < 8; i4++) {
            float4 v = xp[i4];
            *(uint4*)(col + i4*4) = make_uint4(f2tf(v.x), f2tf(v.y), f2tf(v.z), f2tf(v.w));
        }
    }
    int nbase = ng*32 + (lane&3)*2;
    int ebase = mg*32 + (lane>>2);
    {
        float acc[8][4] = {};
#pragma unroll
        for (int hk = 0; hk < 2; hk++) {
            __syncthreads();
            stage_copy<2112,512>(Ws, g_W1c + hk*8448, t);
            __syncthreads();
            gemm_mma<132,264,8>(Ws, ef + hk*64, lane, mg, ng, acc);
        }
        __syncthreads();
#pragma unroll
        for (int nt = 0; nt < 4; nt++) {
            int n = nbase + nt*8;
            float2 bb = *(const float2*)&b1[n];
#pragma unroll
            for (int mt = 0; mt < 2; mt++)
#pragma unroll
            for (int hf = 0; hf < 2; hf++) {
                int el = ebase + mt*16 + hf*8;
                float z0 = acc[mt*4+nt][hf*2+0] + bb.x;
                float z1 = acc[mt*4+nt][hf*2+1] + bb.y;
                *(uint2*)(ef + el*132 + n) = make_uint2(f2tf(z0*sigm(z0)), f2tf(z1*sigm(z1)));
            }
        }
    }
    for (int j = 0; j < 3; j++) {
        float acc[8][4] = {};
#pragma unroll
        for (int hk = 0; hk < 2; hk++) {
            __syncthreads();
            stage_copy<2112,512>(Ws, g_W2c + j*16896 + hk*8448, t);
            __syncthreads();
            gemm_mma<132,264,8>(Ws, ef + hk*64, lane, mg, ng, acc);
        }
#pragma unroll
        for (int nt = 0; nt < 4; nt++) {
            int n = nbase + nt*8;
            float2 bb = *(const float2*)&b2[j*128 + n];
#pragma unroll
            for (int mt = 0; mt < 2; mt++)
#pragma unroll
            for (int hf = 0; hf < 2; hf++) {
                int el = ebase + mt*16 + hf*8;
                *(float2*)&g_rad[(size_t)(e0+el)*384 + j*128 + n] =
                    make_float2(acc[mt*4+nt][hf*2+0] + bb.x, acc[mt*4+nt][hf*2+1] + bb.y);
            }
        }
    }
}

// ---------------- extra ----------------
__global__ void __launch_bounds__(512,2) extra_kernel(
    const float* __restrict__ lng, const float* __restrict__ lnb,
    const float* __restrict__ adot, const int* __restrict__ eidx)
{
    extern __shared__ uint32_t sm[];
    uint32_t* Xs = sm;
    uint32_t* Ws = sm + 16896;
    int* src_s = (int*)(sm + 25344);
    int* tgt_s = src_s + 128;
    int e0 = blockIdx.x * 128, t = threadIdx.x;
    int lane = t & 31, w = t >> 5, mg = w & 3, ng = w >> 2;
    if (t < 128)      src_s[t]     = eidx[e0 + t];
    else if (t < 256) tgt_s[t-128] = eidx[NE + e0 + t - 128];
    __syncthreads();
    {
        int e = t >> 2, q = t & 3;
        const float4* rp = (const float4*)&g_rad[(size_t)(e0+e)*384 + q*32];
        const float4* xp = (q < 2)
            ? (const float4*)&g_xn[(size_t)src_s[e]*576 + q*32]
            : (const float4*)&g_xn[(size_t)tgt_s[e]*576 + (q-2)*32];
        uint32_t* col = Xs + e*132 + q*32;
#pragma unroll
        for (int i4 = 0; i4 < 8; i4++) {
            float4 xv = xp[i4], rv = rp[i4];
            *(uint4*)(col + i4*4) =
                make_uint4(f2tf(xv.x*rv.x), f2tf(xv.y*rv.y), f2tf(xv.z*rv.z), f2tf(xv.w*rv.w));
        }
    }
    int nbase = ng*32 + (lane&3)*2;
    int ebase = mg*32 + (lane>>2);
    for (int oc = 0; oc < 7; oc++) {
        float acc[8][4] = {};
#pragma unroll
        for (int hk = 0; hk < 2; hk++) {
            __syncthreads();
            stage_copy<2112,512>(Ws, g_Wm0c + oc*16896 + hk*8448, t);
            __syncthreads();
            gemm_mma<132,264,8>(Ws, Xs + hk*64, lane, mg, ng, acc);
        }
        if (oc < 2) {
            int h = oc*4 + ng;
#pragma unroll
            for (int mt = 0; mt < 2; mt++)
#pragma unroll
            for (int hf = 0; hf < 2; hf++) {
                int el = ebase + mt*16 + hf*8;
                float sum = 0.f, ssq = 0.f;
#pragma unroll
                for (int nt = 0; nt < 4; nt++) {
                    float v0 = acc[mt*4+nt][hf*2+0], v1 = acc[mt*4+nt][hf*2+1];
                    sum += v0 + v1; ssq += v0*v0 + v1*v1;
                }
                sum += __shfl_xor_sync(0xffffffffu, sum, 1);
                sum += __shfl_xor_sync(0xffffffffu, sum, 2);
                ssq += __shfl_xor_sync(0xffffffffu, ssq, 1);
                ssq += __shfl_xor_sync(0xffffffffu, ssq, 2);
                float m = sum * (1.f/32.f);
                float rs = rsqrtf(ssq * (1.f/32.f) - m*m + 1e-5f);
                float logit = 0.f;
#pragma unroll
                for (int nt = 0; nt < 4; nt++) {
                    int a = nt*8 + (lane&3)*2;
#pragma unroll
                    for (int jj = 0; jj < 2; jj++) {
                        float v = acc[mt*4+nt][hf*2+jj];
                        float an = (v - m)*rs*lng[a+jj] + lnb[a+jj];
                        logit += (0.2f*an + 0.8f*an*sigm(an)) * adot[h*32 + a + jj];
                    }
                }
                logit += __shfl_xor_sync(0xffffffffu, logit, 1);
                logit += __shfl_xor_sync(0xffffffffu, logit, 2);
                if ((lane & 3) == 0) {
                    float ex = __expf(logit);
                    g_e[(size_t)(e0+el)*8 + h] = ex;
                    atomicAdd(&g_den[(size_t)tgt_s[el]*8 + h], ex);
                }
            }
        } else if (oc == 2) {
#pragma unroll
            for (int nt = 0; nt < 4; nt++) {
                int n = nbase + nt*8;
#pragma unroll
                for (int mt = 0; mt < 2; mt++)
#pragma unroll
                for (int hf = 0; hf < 2; hf++) {
                    int el = ebase + mt*16 + hf*8;
                    float z0 = acc[mt*4+nt][hf*2+0], z1 = acc[mt*4+nt][hf*2+1];
                    *(float2*)&g_val0[(size_t)(e0+el)*128 + n] =
                        make_float2(z0*sigm(z0), z1*sigm(z1));
                }
            }
        } else {
            int which = oc - 3;
            float* base = (which < 2) ? g_gdir : g_gten;
            int l = which & 1;
#pragma unroll
            for (int nt = 0; nt < 4; nt++) {
                int n = nbase + nt*8;
#pragma unroll
                for (int mt = 0; mt < 2; mt++)
#pragma unroll
                for (int hf = 0; hf < 2; hf++) {
                    int el = ebase + mt*16 + hf*8;
                    *(float2*)&base[(size_t)(e0+el)*256 + l*128 + n] =
                        make_float2(sigm(acc[mt*4+nt][hf*2+0]), sigm(acc[mt*4+nt][hf*2+1]));
                }
            }
        }
    }
}

// ---------------- fused conv1+conv2 ----------------
__global__ void __launch_bounds__(512,1) conv_kernel(
    const float* __restrict__ rl, const int* __restrict__ eidx)
{
    extern __shared__ uint32_t sm[];
    uint32_t* XV  = sm;            // 16896
    uint32_t* W1s = sm + 16896;    // 16896
    uint32_t* W2s = sm + 33792;    // 16896
    float* rl_s = (float*)(sm + 50688);   // 1024
    float* ee_s = (float*)(sm + 51712);   // 1024
    int* src_s = (int*)(sm + 52736);      // 128
    int* tgt_s = (int*)(sm + 52864);      // 128
    int e0 = blockIdx.x * 128, t = threadIdx.x;
    int lane = t & 31, w = t >> 5, mg = w & 3, ng = w >> 2;
    if (t < 128)      src_s[t]     = eidx[e0 + t];
    else if (t < 256) tgt_s[t-128] = eidx[NE + e0 + t - 128];
    for (int i = t; i < 1024; i += 512) {
        rl_s[i] = rl[(size_t)e0*8 + i];
        ee_s[i] = g_e[(size_t)e0*8 + i];
    }
    int nbase = ng*32 + (lane&3)*2;
    int ebase = mg*32 + (lane>>2);
    int se = t >> 2, sq = t & 3;

    for (int deg = 0; deg <= 2; deg++) {
        __syncthreads();
        stage_copy<4224,512>(W2s, g_Wc2c + deg*16896, t);
        if (deg) stage_copy<4224,512>(W1s, g_Wc1c + deg*16896, t);
        __syncthreads();
        int kbeg = (deg == 0) ? 0 : ((deg == 1) ? 1 : 4);
        int kend = (deg == 0) ? 1 : ((deg == 1) ? 4 : 9);
        for (int k = kbeg; k < kend; k++) {
            if (deg == 0) {
                const float4* vp = (const float4*)&g_val0[(size_t)(e0+se)*128 + sq*32];
                uint32_t* col = XV + se*132 + sq*32;
#pragma unroll
                for (int i4 = 0; i4 < 8; i4++) {
                    float4 v = vp[i4];
                    *(uint4*)(col + i4*4) = make_uint4(f2tf(v.x), f2tf(v.y), f2tf(v.z), f2tf(v.w));
                }
            } else {
                const float4* rp = (const float4*)&g_rad[(size_t)(e0+se)*384 + deg*128 + sq*32];
                const float4* xp = (sq < 2)
                    ? (const float4*)&g_xn[(size_t)src_s[se]*576 + k*64 + sq*32]
                    : (const float4*)&g_xn[(size_t)tgt_s[se]*576 + k*64 + (sq-2)*32];
                uint32_t* col = XV + se*132 + sq*32;
#pragma unroll
                for (int i4 = 0; i4 < 8; i4++) {
                    float4 xv = xp[i4], rv = rp[i4];
                    *(uint4*)(col + i4*4) =
                        make_uint4(f2tf(xv.x*rv.x), f2tf(xv.y*rv.y), f2tf(xv.z*rv.z), f2tf(xv.w*rv.w));
                }
            }
            __syncthreads();
            if (deg) {
                float acc[8][4] = {};
                gemm_mma<132,264,16>(W1s, XV, lane, mg, ng, acc);
                int l = (k < 4) ? 0 : 1;
#pragma unroll
                for (int mt = 0; mt < 2; mt++)
#pragma unroll
                for (int hf = 0; hf < 2; hf++) {
                    int el = ebase + mt*16 + hf*8;
                    size_t ge = (size_t)(e0 + el);
                    float r = rl_s[el*8 + (k-1)];
                    size_t gb = ge*256 + l*128;
                    size_t xb = (size_t)src_s[el]*1024 + (size_t)(k-1)*128;
#pragma unroll
                    for (int nt = 0; nt < 4; nt++) {
                        int n = nbase + nt*8;
                        float2 gd = *(const float2*)&g_gdir[gb + n];
                        float2 gt = *(const float2*)&g_gten[gb + n];
                        float2 xj = *(const float2*)&g_xjp[xb + n];
                        acc[mt*4+nt][hf*2+0] += r*gd.x + xj.x*gt.x;
                        acc[mt*4+nt][hf*2+1] += r*gd.y + xj.y*gt.y;
                    }
                }
                __syncthreads();
#pragma unroll
                for (int mt = 0; mt < 2; mt++)
#pragma unroll
                for (int hf = 0; hf < 2; hf++) {
                    int el = ebase + mt*16 + hf*8;
#pragma unroll
                    for (int nt = 0; nt < 4; nt++) {
                        int n = nbase + nt*8;
                        *(uint2*)(XV + el*132 + n) =
                            make_uint2(f2tf(acc[mt*4+nt][hf*2+0]), f2tf(acc[mt*4+nt][hf*2+1]));
                    }
                }
                __syncthreads();
            }
            float acc[8][4] = {};
            gemm_mma<132,264,16>(W2s, XV, lane, mg, ng, acc);
#pragma unroll
            for (int mt = 0; mt < 2; mt++)
#pragma unroll
            for (int hf = 0; hf < 2; hf++) {
                int el = ebase + mt*16 + hf*8;
                size_t nb = (size_t)tgt_s[el]*1152 + (size_t)k*128;
#pragma unroll
                for (int nt = 0; nt < 4; nt++) {
                    int n = nbase + nt*8;
                    float s = ee_s[el*8 + (n >> 4)];
                    red2(&g_num[nb + n], acc[mt*4+nt][hf*2+0]*s, acc[mt*4+nt][hf*2+1]*s);
                }
            }
            __syncthreads();
        }
    }
}

// ---------------- node GEMMs ----------------
#define P_T0 79
#define P_T1 314
#define P_GRID 705
__device__ __forceinline__ void node_row(int b, int* deg, int* rbase,
                                         int* nslots, int* soff, int* nrows)
{
    if (b < P_T0)      { *deg=0; *rbase=b*128;          *nslots=1; *soff=0; *nrows=10000; }
    else if (b < P_T1) { *deg=1; *rbase=(b-P_T0)*128;   *nslots=3; *soff=1; *nrows=30000; }
    else               { *deg=2; *rbase=(b-P_T1)*128;   *nslots=5; *soff=4; *nrows=50000; }
}

__global__ void __launch_bounds__(256,2) proj_mma(
    const float* __restrict__ x, const float* __restrict__ bp)
{
    extern __shared__ uint32_t sm[];
    uint32_t* Xs = sm;            // 16896
    uint32_t* Ws = sm + 16896;    // 8704
    int deg, rbase, nslots, soff, nrows;
    node_row(blockIdx.x, &deg, &rbase, &nslots, &soff, &nrows);
    int t = threadIdx.x, lane = t & 31, w = t >> 5, mg = w & 3, ng = w >> 2;
    stage_copy<2176,256>(Ws, g_Wpc + deg*8704, t);
    {
        int r = t >> 1, h2 = t & 1;
        int gr = rbase + r;
        uint32_t* col = Xs + r*132 + h2*64;
        if (gr < nrows) {
            int node = gr / nslots, slot = soff + gr % nslots;
            const float4* np = (const float4*)&g_num[(size_t)node*1152 + slot*128 + h2*64];
            float di[4];
#pragma unroll
            for (int q = 0; q < 4; q++) di[q] = 1.f / (g_den[node*8 + h2*4 + q] + 1e-30f);
#pragma unroll
            for (int i = 0; i < 16; i++) {
                float4 v = np[i]; float d = di[i>>2];
                *(uint4*)(col + i*4) = make_uint4(f2tf(v.x*d), f2tf(v.y*d), f2tf(v.z*d), f2tf(v.w*d));
            }
        } else {
#pragma unroll
            for (int i = 0; i < 16; i++) *(uint4*)(col + i*4) = make_uint4(0,0,0,0);
        }
    }
    __syncthreads();
    float acc[8][4] = {};
    gemm_mma<132,136,16>(Ws, Xs, lane, mg, ng, acc);
    int nbase = ng*32 + (lane&3)*2;
    int ebase = mg*32 + (lane>>2);
#pragma unroll
    for (int mt = 0; mt < 2; mt++)
#pragma unroll
    for (int hf = 0; hf < 2; hf++) {
        int gr = rbase + ebase + mt*16 + hf*8;
        if (gr >= nrows) continue;
        int node = gr / nslots, slot = soff + gr % nslots;
        size_t ob = (size_t)node*576 + slot*64;
#pragma unroll
        for (int nt = 0; nt < 4; nt++) {
            int n = nbase + nt*8;
            float b0 = (slot == 0) ? bp[n] : 0.f, b1 = (slot == 0) ? bp[n+1] : 0.f;
            *(float2*)&g_x1[ob + n] = make_float2(
                x[ob + n]   + acc[mt*4+nt][hf*2+0] + b0,
                x[ob + n+1] + acc[mt*4+nt][hf*2+1] + b1);
        }
    }
}

__global__ void __launch_bounds__(256,2) ffn2_mma(
    const float* __restrict__ bf2, float* __restrict__ out)
{
    extern __shared__ uint32_t sm[];
    uint32_t* Xs = sm;
    uint32_t* Ws = sm + 16896;
    int deg, rbase, nslots, soff, nrows;
    node_row(blockIdx.x, &deg, &rbase, &nslots, &soff, &nrows);
    int t = threadIdx.x, lane = t & 31, w = t >> 5, mg = w & 3, ng = w >> 2;
    stage_copy<2176,256>(Ws, g_Wf2c + deg*8704, t);
    {
        int r = t >> 1, h2 = t & 1;
        int gr = rbase + r;
        uint32_t* col = Xs + r*132 + h2*64;
        if (gr < nrows) {
            int node = gr / nslots, slot = soff + gr % nslots;
            const float4* hp = (slot == 0)
                ? (const float4*)&g_gsil[(size_t)node*128 + h2*64]
                : (const float4*)&g_h[(size_t)node*1024 + (size_t)(slot-1)*128 + h2*64];
#pragma unroll
            for (int i = 0; i < 16; i++) {
                float4 v = hp[i];
                *(uint4*)(col + i*4) = make_uint4(f2tf(v.x), f2tf(v.y), f2tf(v.z), f2tf(v.w));
            }
        } else {
#pragma unroll
            for (int i = 0; i < 16; i++) *(uint4*)(col + i*4) = make_uint4(0,0,0,0);
        }
    }
    __syncthreads();
    float acc[8][4] = {};
    gemm_mma<132,136,16>(Ws, Xs, lane, mg, ng, acc);
    int nbase = ng*32 + (lane&3)*2;
    int ebase = mg*32 + (lane>>2);
#pragma unroll
    for (int mt = 0; mt < 2; mt++)
#pragma unroll
    for (int hf = 0; hf < 2; hf++) {
        int gr = rbase + ebase + mt*16 + hf*8;
        if (gr >= nrows) continue;
        int node = gr / nslots, slot = soff + gr % nslots;
        size_t ob = (size_t)node*576 + slot*64;
#pragma unroll
        for (int nt = 0; nt < 4; nt++) {
            int n = nbase + nt*8;
            float b0 = (slot == 0) ? bf2[n] : 0.f, b1 = (slot == 0) ? bf2[n+1] : 0.f;
            *(float2*)&out[ob + n] = make_float2(
                g_x1[ob + n]   + acc[mt*4+nt][hf*2+0] + b0,
                g_x1[ob + n+1] + acc[mt*4+nt][hf*2+1] + b1);
        }
    }
}

#define F_T1 469
#define F_GRID 1251
__global__ void __launch_bounds__(256) ffn1_mma()
{
    extern __shared__ uint32_t sm[];
    uint32_t* Xs = sm;            // 4352
    uint32_t* Ws = sm + 4352;     // 8448
    int b = blockIdx.x, deg, rbase, nslots, soff, nrows;
    if (b < F_T1) { deg=1; rbase=b*64;         nslots=3; soff=1; nrows=30000; }
    else          { deg=2; rbase=(b-F_T1)*64;  nslots=5; soff=4; nrows=50000; }
    int t = threadIdx.x, lane = t & 31, w = t >> 5, mg = w & 1, ng = w >> 1;
    stage_copy<2112,256>(Ws, g_Wf1c + deg*8448, t);
    {
        int r = t >> 2, q = t & 3;
        int gr = rbase + r;
        uint32_t* col = Xs + r*68 + q*16;
        if (gr < nrows) {
            int node = gr / nslots, slot = soff + gr % nslots;
            const float4* yp = (const float4*)&g_yn[(size_t)node*576 + slot*64 + q*16];
#pragma unroll
            for (int i = 0; i < 4; i++) {
                float4 v = yp[i];
                *(uint4*)(col + i*4) = make_uint4(f2tf(v.x), f2tf(v.y), f2tf(v.z), f2tf(v.w));
            }
        } else {
#pragma unroll
            for (int i = 0; i < 4; i++) *(uint4*)(col + i*4) = make_uint4(0,0,0,0);
        }
    }
    __syncthreads();
    float acc[8][4] = {};
    gemm_mma<68,264,8>(Ws, Xs, lane, mg, ng, acc);
    int nbase = ng*32 + (lane&3)*2;
    int ebase = mg*32 + (lane>>2);
#pragma unroll
    for (int mt = 0; mt < 2; mt++)
#pragma unroll
    for (int hf = 0; hf < 2; hf++) {
        int gr = rbase + ebase + mt*16 + hf*8;
        if (gr >= nrows) continue;
        int node = gr / nslots, slot = soff + gr % nslots;
        size_t hb = (size_t)node*1024 + (size_t)(slot-1)*128;
        size_t gsb = (size_t)node*128;
#pragma unroll
        for (int nt = 0; nt < 4; nt++) {
            int n = nbase + nt*8;
            float2 gs = *(const float2*)&g_gsig[gsb + n];
            *(float2*)&g_h[hb + n] = make_float2(
                acc[mt*4+nt][hf*2+0]*gs.x, acc[mt*4+nt][hf*2+1]*gs.y);
        }
    }
}

// ---------------- launch ----------------
extern "C" void kernel_launch(void* const* d_in, const int* in_sizes, int n_in,
                              void* d_out, int out_size)
{
    const float* x     = (const float*)d_in[0];
    const float* edist = (const float*)d_in[1];
    const float* rl    = (const float*)d_in[2];
    const float* semb  = (const float*)d_in[3];
    const float* temb  = (const float*)d_in[4];
    const float* W1    = (const float*)d_in[5];
    const float* b1    = (const float*)d_in[6];
    const float* W2    = (const float*)d_in[7];
    const float* b2    = (const float*)d_in[8];
    const float* Wc1   = (const float*)d_in[9];
    const float* Wm0   = (const float*)d_in[10];
    const float* lng   = (const float*)d_in[11];
    const float* lnb   = (const float*)d_in[12];
    const float* adot  = (const float*)d_in[13];
    const float* Wxj   = (const float*)d_in[14];
    const float* Wc2   = (const float*)d_in[15];
    const float* Wp    = (const float*)d_in[16];
    const float* bp    = (const float*)d_in[17];
    const float* Wg    = (const float*)d_in[18];
    const float* bg    = (const float*)d_in[19];
    const float* Wf1   = (const float*)d_in[20];
    const float* Wf2   = (const float*)d_in[22];
    const float* bf2   = (const float*)d_in[23];
    const int*   anum  = (const int*)d_in[24];
    const int*   eidx  = (const int*)d_in[25];
    float* out = (float*)d_out;

    float *p_xn, *p_x1, *p_yn;
    cudaGetSymbolAddress((void**)&p_xn, g_xn);
    cudaGetSymbolAddress((void**)&p_x1, g_x1);
    cudaGetSymbolAddress((void**)&p_yn, g_yn);

    static bool attr_set = false;
    if (!attr_set) {
        cudaFuncSetAttribute(rad_kernel,   cudaFuncAttributeMaxDynamicSharedMemorySize, 102400);
        cudaFuncSetAttribute(extra_kernel, cudaFuncAttributeMaxDynamicSharedMemorySize, 102400);
        cudaFuncSetAttribute(conv_kernel,  cudaFuncAttributeMaxDynamicSharedMemorySize, 211968);
        cudaFuncSetAttribute(proj_mma,     cudaFuncAttributeMaxDynamicSharedMemorySize, 102400);
        cudaFuncSetAttribute(ffn2_mma,     cudaFuncAttributeMaxDynamicSharedMemorySize, 102400);
        cudaFuncSetAttribute(ffn1_mma,     cudaFuncAttributeMaxDynamicSharedMemorySize, 51200);
        cudaFuncSetAttribute(xjp_mma,      cudaFuncAttributeMaxDynamicSharedMemorySize, 51200);
        cudaFuncSetAttribute(gate_mma,     cudaFuncAttributeMaxDynamicSharedMemorySize, 51200);
        attr_set = true;
    }

    wconv_kernel<<<(WCONV_N + 255)/256, 256>>>(W1, W2, Wm0, Wc1, Wc2, Wp, Wf1, Wf2, Wxj, Wg);
    zero_kernel<<<(NN*1152/4 + 255)/256, 256>>>();
    enorm_kernel<<<NN/4, 256>>>(x, p_xn);
    xjp_mma<<<XJ_GRID, 256, 51200>>>();
    rad_kernel<<<NE/128, 512, 102400>>>(edist, semb, temb, b1, b2, anum, eidx);
    extra_kernel<<<NE/128, 512, 102400>>>(lng, lnb, adot, eidx);
    conv_kernel<<<NE/128, 512, 211968>>>(rl, eidx);
    proj_mma<<<P_GRID, 256, 102400>>>(x, bp);
    enorm_kernel<<<NN/4, 256>>>(p_x1, p_yn);
    gate_mma<<<GATE_GRID, 256, 51200>>>(bg);
    ffn1_mma<<<F_GRID, 256, 51200>>>();
    ffn2_mma<<<P_GRID, 256, 102400>>>(bf2, out);
}

// round 11
// speedup vs baseline: 1.0871x; 1.0871x over previous
#include <cuda_runtime.h>
#include <cstdint>

#define NN 10000
#define NE 80000

__device__ float g_xn  [NN*576];
__device__ float g_rad [NE*384];
__device__ float g_val0[NE*128];
__device__ float g_gdir[NE*256];
__device__ float g_gten[NE*256];
__device__ float g_e   [NE*8];
__device__ float g_xjp [NN*1024];
__device__ float g_num [NN*1152];
__device__ float g_den [NN*8];
__device__ float g_x1  [NN*576];
__device__ float g_yn  [NN*576];
__device__ float g_h   [NN*1024];
__device__ float g_gsil[NN*128];
__device__ float g_gsig[NN*128];

// pre-converted tf32 weights in fragment-interleaved SMEM-image layout
__device__ __align__(16) uint32_t g_W1c [16896];
__device__ __align__(16) uint32_t g_W2c [50688];
__device__ __align__(16) uint32_t g_Wm0c[118272];
__device__ __align__(16) uint32_t g_Wc1c[50688];
__device__ __align__(16) uint32_t g_Wc2c[50688];
__device__ __align__(16) uint32_t g_Wpc [26112];
__device__ __align__(16) uint32_t g_Wf1c[25344];
__device__ __align__(16) uint32_t g_Wf2c[26112];
__device__ __align__(16) uint32_t g_Wxjc[8448];
__device__ __align__(16) uint32_t g_Wgc [8448];

__device__ __forceinline__ float sigm(float z) { return 1.f / (1.f + __expf(-z)); }

__device__ __forceinline__ uint32_t f2tf(float x) {
    uint32_t r; asm("cvt.rna.tf32.f32 %0, %1;" : "=r"(r) : "f"(x)); return r;
}
__device__ __forceinline__ void red2(float* p, float a, float b) {
    asm volatile("red.global.add.v2.f32 [%0], {%1,%2};" :: "l"(p), "f"(a), "f"(b) : "memory");
}
__device__ __forceinline__ void mma8(float* d, uint32_t a0,uint32_t a1,uint32_t a2,uint32_t a3,
                                     uint32_t b0,uint32_t b1) {
    asm volatile("mma.sync.aligned.m16n8k8.row.col.f32.tf32.tf32.f32 "
                 "{%0,%1,%2,%3},{%4,%5,%6,%7},{%8,%9},{%0,%1,%2,%3};"
                 : "+f"(d[0]),"+f"(d[1]),"+f"(d[2]),"+f"(d[3])
                 : "r"(a0),"r"(a1),"r"(a2),"r"(a3),"r"(b0),"r"(b1));
}

// ---- cp.async helpers ----
__device__ __forceinline__ void cp16(uint32_t saddr, const uint32_t* src) {
    asm volatile("cp.async.cg.shared.global [%0], [%1], 16;" :: "r"(saddr), "l"(src));
}
#define CP_COMMIT() asm volatile("cp.async.commit_group;" ::: "memory")
#define CP_WAIT0()  asm volatile("cp.async.wait_group 0;" ::: "memory")
#define CP_WAIT1()  asm volatile("cp.async.wait_group 1;" ::: "memory")

// copy N4 uint4 chunks, then commit a group
template<int N4, int NT>
__device__ __forceinline__ void cp_chunk(uint32_t* dst, const uint32_t* __restrict__ src, int t) {
    uint32_t d = (uint32_t)__cvta_generic_to_shared(dst);
    for (int i = t; i < N4; i += NT) cp16(d + i*16, src + i*4);
    CP_COMMIT();
}

__device__ __forceinline__ int pairpos(int k, int n, int QS) {
    return (k>>3)*4*QS + (k&3)*QS + n*2 + ((k>>2)&1);
}

// Warp tile 32 rows x 32 cols.
template<int XST, int QS, int NK>
__device__ __forceinline__ void gemm_mma(const uint32_t* __restrict__ Ws,
                                         const uint32_t* __restrict__ Xs,
                                         int lane, int mg, int ng, float acc[8][4])
{
    const uint32_t* xb = Xs + (mg*32 + (lane>>2))*XST + (lane&3);
    const uint32_t* wb = Ws + (lane&3)*QS + (ng*32 + (lane>>2))*2;
#pragma unroll 4
    for (int kk = 0; kk < NK; kk++) {
        const uint32_t* xp = xb + kk*8;
        uint32_t a00 = xp[0],      a01 = xp[8*XST],   a02 = xp[4],        a03 = xp[8*XST+4];
        uint32_t a10 = xp[16*XST], a11 = xp[24*XST],  a12 = xp[16*XST+4], a13 = xp[24*XST+4];
        const uint32_t* wp = wb + kk*4*QS;
        uint2 b[4];
#pragma unroll
        for (int nt = 0; nt < 4; nt++) b[nt] = *(const uint2*)(wp + nt*16);
#pragma unroll
        for (int nt = 0; nt < 4; nt++) {
            mma8(acc[nt],   a00,a01,a02,a03, b[nt].x, b[nt].y);
            mma8(acc[4+nt], a10,a11,a12,a13, b[nt].x, b[nt].y);
        }
    }
}

// ---------------- weight pre-conversion ----------------
__global__ void __launch_bounds__(256) wconv_kernel(
    const float* __restrict__ W1, const float* __restrict__ W2,
    const float* __restrict__ Wm0, const float* __restrict__ Wc1,
    const float* __restrict__ Wc2, const float* __restrict__ Wp,
    const float* __restrict__ Wf1, const float* __restrict__ Wf2,
    const float* __restrict__ Wxj, const float* __restrict__ Wg)
{
    int i = blockIdx.x*256 + threadIdx.x;
    if (i < 16384) { int k=i>>7, n=i&127;
        g_W1c[pairpos(k,n,264)] = f2tf(W1[i]); return; } i -= 16384;
    if (i < 49152) { int j=i/16384, r=i&16383, k=r>>7, n=r&127;
        g_W2c[j*16896 + pairpos(k,n,264)] = f2tf(W2[k*384 + j*128 + n]); return; } i -= 49152;
    if (i < 114688){ int j=i/16384, r=i&16383, k=r>>7, n=r&127;
        g_Wm0c[j*16896 + pairpos(k,n,264)] = f2tf(Wm0[k*896 + j*128 + n]); return; } i -= 114688;
    if (i < 49152) { int d=i>>14, r=i&16383, k=r>>7, n=r&127;
        g_Wc1c[d*16896 + pairpos(k,n,264)] = f2tf(Wc1[i]); return; } i -= 49152;
    if (i < 49152) { int d=i>>14, r=i&16383, k=r>>7, n=r&127;
        g_Wc2c[d*16896 + pairpos(k,n,264)] = f2tf(Wc2[i]); return; } i -= 49152;
    if (i < 24576) { int d=i>>13, r=i&8191, k=r>>6, n=r&63;
        g_Wpc[d*8704 + pairpos(k,n,136)] = f2tf(Wp[i]); return; } i -= 24576;
    if (i < 16384) { int d=(i>>13)+1, r=i&8191, k=r>>7, n=r&127;
        g_Wf1c[d*8448 + pairpos(k,n,264)] = f2tf(Wf1[d*8192 + r]); return; } i -= 16384;
    if (i < 24576) { int d=i>>13, r=i&8191, k=r>>6, n=r&63;
        g_Wf2c[d*8704 + pairpos(k,n,136)] = f2tf(Wf2[i]); return; } i -= 24576;
    if (i < 8192)  { int k=i>>7, n=i&127;
        g_Wxjc[pairpos(k,n,264)] = f2tf(Wxj[i]); return; } i -= 8192;
    if (i < 8192)  { int k=i>>7, n=i&127;
        g_Wgc[pairpos(k,n,264)] = f2tf(Wg[i]); return; }
}
#define WCONV_N 360448

__global__ void zero_kernel() {
    size_t i = (size_t)blockIdx.x * blockDim.x + threadIdx.x;
    if (i < NN*1152/4) ((float4*)g_num)[i] = make_float4(0.f,0.f,0.f,0.f);
    if (i < NN*8)      g_den[i] = 0.f;
}

// ---------------- enorm ----------------
__global__ void __launch_bounds__(256) enorm_kernel(const float* __restrict__ src, float* __restrict__ dst) {
    int n = blockIdx.x*4 + (threadIdx.x >> 6);
    int c = threadIdx.x & 63;
    const float* p = src + (size_t)n*576 + c;
    float v[9];
#pragma unroll
    for (int k = 0; k < 9; k++) v[k] = p[k*64];
    float s0 = v[0]*v[0];
    float s1 = v[1]*v[1] + v[2]*v[2] + v[3]*v[3];
    float s2 = v[4]*v[4] + v[5]*v[5] + v[6]*v[6] + v[7]*v[7] + v[8]*v[8];
#pragma unroll
    for (int off = 16; off; off >>= 1) {
        s0 += __shfl_xor_sync(0xffffffffu, s0, off);
        s1 += __shfl_xor_sync(0xffffffffu, s1, off);
        s2 += __shfl_xor_sync(0xffffffffu, s2, off);
    }
    __shared__ float red[4][3][2];
    int g = threadIdx.x >> 6, hw = (c >> 5);
    if ((c & 31) == 0) { red[g][0][hw] = s0; red[g][1][hw] = s1; red[g][2][hw] = s2; }
    __syncthreads();
    float sc0 = rsqrtf((red[g][0][0]+red[g][0][1]) * (1.f/64.f)  + 1e-6f);
    float sc1 = rsqrtf((red[g][1][0]+red[g][1][1]) * (1.f/192.f) + 1e-6f);
    float sc2 = rsqrtf((red[g][2][0]+red[g][2][1]) * (1.f/320.f) + 1e-6f);
    float* q = dst + (size_t)n*576 + c;
    q[0] = v[0]*sc0;
#pragma unroll
    for (int k = 1; k < 4; k++) q[k*64] = v[k]*sc1;
#pragma unroll
    for (int k = 4; k < 9; k++) q[k*64] = v[k]*sc2;
}

// ---------------- xjp: 80000 rows x 128, K=64 ----------------
#define XJ_GRID 1250
__global__ void __launch_bounds__(256) xjp_mma()
{
    extern __shared__ uint32_t sm[];
    uint32_t* Xs = sm;            // 4352
    uint32_t* Ws = sm + 4352;     // 8448
    int rbase = blockIdx.x * 64;
    int t = threadIdx.x, lane = t & 31, w = t >> 5, mg = w & 1, ng = w >> 1;
    cp_chunk<2112,256>(Ws, g_Wxjc, t);
    {
        int r = t >> 2, q = t & 3;
        int gr = rbase + r;
        int node = gr >> 3, slot = 1 + (gr & 7);
        const float4* yp = (const float4*)&g_xn[(size_t)node*576 + slot*64 + q*16];
        uint32_t* col = Xs + r*68 + q*16;
#pragma unroll
        for (int i = 0; i < 4; i++) {
            float4 v = yp[i];
            *(uint4*)(col + i*4) = make_uint4(f2tf(v.x), f2tf(v.y), f2tf(v.z), f2tf(v.w));
        }
    }
    CP_WAIT0();
    __syncthreads();
    float acc[8][4] = {};
    gemm_mma<68,264,8>(Ws, Xs, lane, mg, ng, acc);
    int nbase = ng*32 + (lane&3)*2;
    int ebase = mg*32 + (lane>>2);
#pragma unroll
    for (int mt = 0; mt < 2; mt++)
#pragma unroll
    for (int hf = 0; hf < 2; hf++) {
        int gr = rbase + ebase + mt*16 + hf*8;
        int node = gr >> 3, slot = gr & 7;
        size_t ob = (size_t)node*1024 + (size_t)slot*128;
#pragma unroll
        for (int nt = 0; nt < 4; nt++) {
            int n = nbase + nt*8;
            *(float2*)&g_xjp[ob + n] =
                make_float2(acc[mt*4+nt][hf*2+0], acc[mt*4+nt][hf*2+1]);
        }
    }
}

// ---------------- gate: 10000 rows x 128, K=64 ----------------
#define GATE_GRID 157
__global__ void __launch_bounds__(256) gate_mma(const float* __restrict__ bg)
{
    extern __shared__ uint32_t sm[];
    uint32_t* Xs = sm;
    uint32_t* Ws = sm + 4352;
    int rbase = blockIdx.x * 64;
    int t = threadIdx.x, lane = t & 31, w = t >> 5, mg = w & 1, ng = w >> 1;
    cp_chunk<2112,256>(Ws, g_Wgc, t);
    {
        int r = t >> 2, q = t & 3;
        int node = rbase + r;
        uint32_t* col = Xs + r*68 + q*16;
        if (node < NN) {
            const float4* yp = (const float4*)&g_yn[(size_t)node*576 + q*16];
#pragma unroll
            for (int i = 0; i < 4; i++) {
                float4 v = yp[i];
                *(uint4*)(col + i*4) = make_uint4(f2tf(v.x), f2tf(v.y), f2tf(v.z), f2tf(v.w));
            }
        } else {
#pragma unroll
            for (int i = 0; i < 4; i++) *(uint4*)(col + i*4) = make_uint4(0,0,0,0);
        }
    }
    CP_WAIT0();
    __syncthreads();
    float acc[8][4] = {};
    gemm_mma<68,264,8>(Ws, Xs, lane, mg, ng, acc);
    int nbase = ng*32 + (lane&3)*2;
    int ebase = mg*32 + (lane>>2);
#pragma unroll
    for (int mt = 0; mt < 2; mt++)
#pragma unroll
    for (int hf = 0; hf < 2; hf++) {
        int node = rbase + ebase + mt*16 + hf*8;
        if (node >= NN) continue;
        size_t ob = (size_t)node*128;
#pragma unroll
        for (int nt = 0; nt < 4; nt++) {
            int n = nbase + nt*8;
            float z0 = acc[mt*4+nt][hf*2+0] + bg[n];
            float z1 = acc[mt*4+nt][hf*2+1] + bg[n+1];
            float s0 = sigm(z0), s1 = sigm(z1);
            *(float2*)&g_gsil[ob + n] = make_float2(z0*s0, z1*s1);
            *(float2*)&g_gsig[ob + n] = make_float2(s0, s1);
        }
    }
}

// ---------------- radial MLP: 128 edges/block, 16-quarter weight pipeline ----------------
__global__ void __launch_bounds__(512,2) rad_kernel(
    const float* __restrict__ edist, const float* __restrict__ semb,
    const float* __restrict__ temb,  const float* __restrict__ b1,
    const float* __restrict__ b2,    const int* __restrict__ anum,
    const int* __restrict__ eidx)
{
    extern __shared__ uint32_t sm[];
    uint32_t* ef = sm;            // 16896
    uint32_t* Ws = sm + 16896;    // 8448 = 2 x 4224 quarter buffers
    int* zsrc = (int*)(sm + 25344);
    int* ztgt = zsrc + 128;
    int e0 = blockIdx.x * 128, t = threadIdx.x;
    int lane = t & 31, w = t >> 5, mg = w & 3, ng = w >> 2;
    auto qsrc = [](int m) { return m < 4 ? g_W1c + m*4224 : g_W2c + (m-4)*4224; };
    cp_chunk<1056,512>(Ws,        qsrc(0), t);
    cp_chunk<1056,512>(Ws + 4224, qsrc(1), t);
    if (t < 128)      zsrc[t]     = anum[eidx[e0 + t]];
    else if (t < 256) ztgt[t-128] = anum[eidx[NE + e0 + t - 128]];
    __syncthreads();
    {
        int e = t >> 2, q = t & 3;
        const float4* xp;
        if (q < 2)      xp = (const float4*)&edist[(size_t)(e0+e)*64 + q*32];
        else if (q==2)  xp = (const float4*)&semb[(size_t)zsrc[e]*32];
        else            xp = (const float4*)&temb[(size_t)ztgt[e]*32];
        uint32_t* col = ef + e*132 + q*32;
#pragma unroll
        for (int i4 = 0; i4 < 8; i4++) {
            float4 v = xp[i4];
            *(uint4*)(col + i4*4) = make_uint4(f2tf(v.x), f2tf(v.y), f2tf(v.z), f2tf(v.w));
        }
    }
    int nbase = ng*32 + (lane&3)*2;
    int ebase = mg*32 + (lane>>2);
    int m = 0;
    {   // layer 1 (quarters 0..3)
        float acc[8][4] = {};
        for (int q = 0; q < 4; q++, m++) {
            if (m + 1 < 16) CP_WAIT1(); else CP_WAIT0();
            __syncthreads();
            gemm_mma<132,264,4>(Ws + (m&1)*4224, ef + q*32, lane, mg, ng, acc);
            __syncthreads();
            if (m + 2 < 16) cp_chunk<1056,512>(Ws + (m&1)*4224, qsrc(m+2), t);
        }
#pragma unroll
        for (int nt = 0; nt < 4; nt++) {
            int n = nbase + nt*8;
            float2 bb = *(const float2*)&b1[n];
#pragma unroll
            for (int mt = 0; mt < 2; mt++)
#pragma unroll
            for (int hf = 0; hf < 2; hf++) {
                int el = ebase + mt*16 + hf*8;
                float z0 = acc[mt*4+nt][hf*2+0] + bb.x;
                float z1 = acc[mt*4+nt][hf*2+1] + bb.y;
                *(uint2*)(ef + el*132 + n) = make_uint2(f2tf(z0*sigm(z0)), f2tf(z1*sigm(z1)));
            }
        }
    }
    for (int j = 0; j < 3; j++) {
        float acc[8][4] = {};
        for (int q = 0; q < 4; q++, m++) {
            if (m + 1 < 16) CP_WAIT1(); else CP_WAIT0();
            __syncthreads();
            gemm_mma<132,264,4>(Ws + (m&1)*4224, ef + q*32, lane, mg, ng, acc);
            __syncthreads();
            if (m + 2 < 16) cp_chunk<1056,512>(Ws + (m&1)*4224, qsrc(m+2), t);
        }
#pragma unroll
        for (int nt = 0; nt < 4; nt++) {
            int n = nbase + nt*8;
            float2 bb = *(const float2*)&b2[j*128 + n];
#pragma unroll
            for (int mt = 0; mt < 2; mt++)
#pragma unroll
            for (int hf = 0; hf < 2; hf++) {
                int el = ebase + mt*16 + hf*8;
                *(float2*)&g_rad[(size_t)(e0+el)*384 + j*128 + n] =
                    make_float2(acc[mt*4+nt][hf*2+0] + bb.x, acc[mt*4+nt][hf*2+1] + bb.y);
            }
        }
    }
}

// ---------------- extra: 28-quarter weight pipeline ----------------
__global__ void __launch_bounds__(512,2) extra_kernel(
    const float* __restrict__ lng, const float* __restrict__ lnb,
    const float* __restrict__ adot, const int* __restrict__ eidx)
{
    extern __shared__ uint32_t sm[];
    uint32_t* Xs = sm;
    uint32_t* Ws = sm + 16896;
    int* src_s = (int*)(sm + 25344);
    int* tgt_s = src_s + 128;
    int e0 = blockIdx.x * 128, t = threadIdx.x;
    int lane = t & 31, w = t >> 5, mg = w & 3, ng = w >> 2;
    cp_chunk<1056,512>(Ws,        g_Wm0c,        t);
    cp_chunk<1056,512>(Ws + 4224, g_Wm0c + 4224, t);
    if (t < 128)      src_s[t]     = eidx[e0 + t];
    else if (t < 256) tgt_s[t-128] = eidx[NE + e0 + t - 128];
    __syncthreads();
    {
        int e = t >> 2, q = t & 3;
        const float4* rp = (const float4*)&g_rad[(size_t)(e0+e)*384 + q*32];
        const float4* xp = (q < 2)
            ? (const float4*)&g_xn[(size_t)src_s[e]*576 + q*32]
            : (const float4*)&g_xn[(size_t)tgt_s[e]*576 + (q-2)*32];
        uint32_t* col = Xs + e*132 + q*32;
#pragma unroll
        for (int i4 = 0; i4 < 8; i4++) {
            float4 xv = xp[i4], rv = rp[i4];
            *(uint4*)(col + i4*4) =
                make_uint4(f2tf(xv.x*rv.x), f2tf(xv.y*rv.y), f2tf(xv.z*rv.z), f2tf(xv.w*rv.w));
        }
    }
    int nbase = ng*32 + (lane&3)*2;
    int ebase = mg*32 + (lane>>2);
    int m = 0;
    for (int oc = 0; oc < 7; oc++) {
        float acc[8][4] = {};
        for (int q = 0; q < 4; q++, m++) {
            if (m + 1 < 28) CP_WAIT1(); else CP_WAIT0();
            __syncthreads();
            gemm_mma<132,264,4>(Ws + (m&1)*4224, Xs + q*32, lane, mg, ng, acc);
            __syncthreads();
            if (m + 2 < 28) cp_chunk<1056,512>(Ws + (m&1)*4224, g_Wm0c + (m+2)*4224, t);
        }
        if (oc < 2) {
            int h = oc*4 + ng;
#pragma unroll
            for (int mt = 0; mt < 2; mt++)
#pragma unroll
            for (int hf = 0; hf < 2; hf++) {
                int el = ebase + mt*16 + hf*8;
                float sum = 0.f, ssq = 0.f;
#pragma unroll
                for (int nt = 0; nt < 4; nt++) {
                    float v0 = acc[mt*4+nt][hf*2+0], v1 = acc[mt*4+nt][hf*2+1];
                    sum += v0 + v1; ssq += v0*v0 + v1*v1;
                }
                sum += __shfl_xor_sync(0xffffffffu, sum, 1);
                sum += __shfl_xor_sync(0xffffffffu, sum, 2);
                ssq += __shfl_xor_sync(0xffffffffu, ssq, 1);
                ssq += __shfl_xor_sync(0xffffffffu, ssq, 2);
                float mean = sum * (1.f/32.f);
                float rs = rsqrtf(ssq * (1.f/32.f) - mean*mean + 1e-5f);
                float logit = 0.f;
#pragma unroll
                for (int nt = 0; nt < 4; nt++) {
                    int a = nt*8 + (lane&3)*2;
#pragma unroll
                    for (int jj = 0; jj < 2; jj++) {
                        float v = acc[mt*4+nt][hf*2+jj];
                        float an = (v - mean)*rs*lng[a+jj] + lnb[a+jj];
                        logit += (0.2f*an + 0.8f*an*sigm(an)) * adot[h*32 + a + jj];
                    }
                }
                logit += __shfl_xor_sync(0xffffffffu, logit, 1);
                logit += __shfl_xor_sync(0xffffffffu, logit, 2);
                if ((lane & 3) == 0) {
                    float ex = __expf(logit);
                    g_e[(size_t)(e0+el)*8 + h] = ex;
                    atomicAdd(&g_den[(size_t)tgt_s[el]*8 + h], ex);
                }
            }
        } else if (oc == 2) {
#pragma unroll
            for (int nt = 0; nt < 4; nt++) {
                int n = nbase + nt*8;
#pragma unroll
                for (int mt = 0; mt < 2; mt++)
#pragma unroll
                for (int hf = 0; hf < 2; hf++) {
                    int el = ebase + mt*16 + hf*8;
                    float z0 = acc[mt*4+nt][hf*2+0], z1 = acc[mt*4+nt][hf*2+1];
                    *(float2*)&g_val0[(size_t)(e0+el)*128 + n] =
                        make_float2(z0*sigm(z0), z1*sigm(z1));
                }
            }
        } else {
            int which = oc - 3;
            float* base = (which < 2) ? g_gdir : g_gten;
            int l = which & 1;
#pragma unroll
            for (int nt = 0; nt < 4; nt++) {
                int n = nbase + nt*8;
#pragma unroll
                for (int mt = 0; mt < 2; mt++)
#pragma unroll
                for (int hf = 0; hf < 2; hf++) {
                    int el = ebase + mt*16 + hf*8;
                    *(float2*)&base[(size_t)(e0+el)*256 + l*128 + n] =
                        make_float2(sigm(acc[mt*4+nt][hf*2+0]), sigm(acc[mt*4+nt][hf*2+1]));
                }
            }
        }
    }
}

// ---------------- fused conv1+conv2 with epilogue prefetch ----------------
__global__ void __launch_bounds__(512,1) conv_kernel(
    const float* __restrict__ rl, const int* __restrict__ eidx)
{
    extern __shared__ uint32_t sm[];
    uint32_t* XV  = sm;            // 16896
    uint32_t* W1s = sm + 16896;    // 16896
    uint32_t* W2s = sm + 33792;    // 16896
    float* rl_s = (float*)(sm + 50688);
    float* ee_s = (float*)(sm + 51712);
    int* src_s = (int*)(sm + 52736);
    int* tgt_s = (int*)(sm + 52864);
    int e0 = blockIdx.x * 128, t = threadIdx.x;
    int lane = t & 31, w = t >> 5, mg = w & 3, ng = w >> 2;
    if (t < 128)      src_s[t]     = eidx[e0 + t];
    else if (t < 256) tgt_s[t-128] = eidx[NE + e0 + t - 128];
    for (int i = t; i < 1024; i += 512) {
        rl_s[i] = rl[(size_t)e0*8 + i];
        ee_s[i] = g_e[(size_t)e0*8 + i];
    }
    int nbase = ng*32 + (lane&3)*2;
    int ebase = mg*32 + (lane>>2);
    int se = t >> 2, sq = t & 3;

    for (int deg = 0; deg <= 2; deg++) {
        __syncthreads();   // prior reads of W buffers + XV done
        cp_chunk<4224,512>(W2s, g_Wc2c + deg*16896, t);
        if (deg) cp_chunk<4224,512>(W1s, g_Wc1c + deg*16896, t);
        int kbeg = (deg == 0) ? 0 : ((deg == 1) ? 1 : 4);
        int kend = (deg == 0) ? 1 : ((deg == 1) ? 4 : 9);
        for (int k = kbeg; k < kend; k++) {
            // ---- stage XV (overlaps the weight cp.async on first slot) ----
            if (deg == 0) {
                const float4* vp = (const float4*)&g_val0[(size_t)(e0+se)*128 + sq*32];
                uint32_t* col = XV + se*132 + sq*32;
#pragma unroll
                for (int i4 = 0; i4 < 8; i4++) {
                    float4 v = vp[i4];
                    *(uint4*)(col + i4*4) = make_uint4(f2tf(v.x), f2tf(v.y), f2tf(v.z), f2tf(v.w));
                }
            } else {
                const float4* rp = (const float4*)&g_rad[(size_t)(e0+se)*384 + deg*128 + sq*32];
                const float4* xp = (sq < 2)
                    ? (const float4*)&g_xn[(size_t)src_s[se]*576 + k*64 + sq*32]
                    : (const float4*)&g_xn[(size_t)tgt_s[se]*576 + k*64 + (sq-2)*32];
                uint32_t* col = XV + se*132 + sq*32;
#pragma unroll
                for (int i4 = 0; i4 < 8; i4++) {
                    float4 xv = xp[i4], rv = rp[i4];
                    *(uint4*)(col + i4*4) =
                        make_uint4(f2tf(xv.x*rv.x), f2tf(xv.y*rv.y), f2tf(xv.z*rv.z), f2tf(xv.w*rv.w));
                }
            }
            if (k == kbeg) CP_WAIT0();
            __syncthreads();
            if (deg) {
                // prefetch epilogue operands BEFORE the MMA wall
                int l = (k < 4) ? 0 : 1;
                float2 pgd[4][4], pgt[4][4], pxj[4][4];
#pragma unroll
                for (int mh = 0; mh < 4; mh++) {
                    int el = ebase + (mh>>1)*16 + (mh&1)*8;
                    size_t gb = (size_t)(e0 + el)*256 + l*128;
                    size_t xb = (size_t)src_s[el]*1024 + (size_t)(k-1)*128;
#pragma unroll
                    for (int nt = 0; nt < 4; nt++) {
                        int n = nbase + nt*8;
                        pgd[mh][nt] = *(const float2*)&g_gdir[gb + n];
                        pgt[mh][nt] = *(const float2*)&g_gten[gb + n];
                        pxj[mh][nt] = *(const float2*)&g_xjp[xb + n];
                    }
                }
                float acc[8][4] = {};
                gemm_mma<132,264,16>(W1s, XV, lane, mg, ng, acc);
#pragma unroll
                for (int mh = 0; mh < 4; mh++) {
                    int mt = mh >> 1, hf = mh & 1;
                    int el = ebase + mt*16 + hf*8;
                    float r = rl_s[el*8 + (k-1)];
#pragma unroll
                    for (int nt = 0; nt < 4; nt++) {
                        acc[mt*4+nt][hf*2+0] += r*pgd[mh][nt].x + pxj[mh][nt].x*pgt[mh][nt].x;
                        acc[mt*4+nt][hf*2+1] += r*pgd[mh][nt].y + pxj[mh][nt].y*pgt[mh][nt].y;
                    }
                }
                __syncthreads();
#pragma unroll
                for (int mt = 0; mt < 2; mt++)
#pragma unroll
                for (int hf = 0; hf < 2; hf++) {
                    int el = ebase + mt*16 + hf*8;
#pragma unroll
                    for (int nt = 0; nt < 4; nt++) {
                        int n = nbase + nt*8;
                        *(uint2*)(XV + el*132 + n) =
                            make_uint2(f2tf(acc[mt*4+nt][hf*2+0]), f2tf(acc[mt*4+nt][hf*2+1]));
                    }
                }
                __syncthreads();
            }
            float acc[8][4] = {};
            gemm_mma<132,264,16>(W2s, XV, lane, mg, ng, acc);
#pragma unroll
            for (int mt = 0; mt < 2; mt++)
#pragma unroll
            for (int hf = 0; hf < 2; hf++) {
                int el = ebase + mt*16 + hf*8;
                size_t nb = (size_t)tgt_s[el]*1152 + (size_t)k*128;
#pragma unroll
                for (int nt = 0; nt < 4; nt++) {
                    int n = nbase + nt*8;
                    float s = ee_s[el*8 + (n >> 4)];
                    red2(&g_num[nb + n], acc[mt*4+nt][hf*2+0]*s, acc[mt*4+nt][hf*2+1]*s);
                }
            }
            __syncthreads();
        }
    }
}

// ---------------- node GEMMs ----------------
#define P_T0 79
#define P_T1 314
#define P_GRID 705
__device__ __forceinline__ void node_row(int b, int* deg, int* rbase,
                                         int* nslots, int* soff, int* nrows)
{
    if (b < P_T0)      { *deg=0; *rbase=b*128;          *nslots=1; *soff=0; *nrows=10000; }
    else if (b < P_T1) { *deg=1; *rbase=(b-P_T0)*128;   *nslots=3; *soff=1; *nrows=30000; }
    else               { *deg=2; *rbase=(b-P_T1)*128;   *nslots=5; *soff=4; *nrows=50000; }
}

__global__ void __launch_bounds__(256,2) proj_mma(
    const float* __restrict__ x, const float* __restrict__ bp)
{
    extern __shared__ uint32_t sm[];
    uint32_t* Xs = sm;            // 16896
    uint32_t* Ws = sm + 16896;    // 8704
    int deg, rbase, nslots, soff, nrows;
    node_row(blockIdx.x, &deg, &rbase, &nslots, &soff, &nrows);
    int t = threadIdx.x, lane = t & 31, w = t >> 5, mg = w & 3, ng = w >> 2;
    cp_chunk<2176,256>(Ws, g_Wpc + deg*8704, t);
    {
        int r = t >> 1, h2 = t & 1;
        int gr = rbase + r;
        uint32_t* col = Xs + r*132 + h2*64;
        if (gr < nrows) {
            int node = gr / nslots, slot = soff + gr % nslots;
            const float4* np = (const float4*)&g_num[(size_t)node*1152 + slot*128 + h2*64];
            float di[4];
#pragma unroll
            for (int q = 0; q < 4; q++) di[q] = 1.f / (g_den[node*8 + h2*4 + q] + 1e-30f);
#pragma unroll
            for (int i = 0; i < 16; i++) {
                float4 v = np[i]; float d = di[i>>2];
                *(uint4*)(col + i*4) = make_uint4(f2tf(v.x*d), f2tf(v.y*d), f2tf(v.z*d), f2tf(v.w*d));
            }
        } else {
#pragma unroll
            for (int i = 0; i < 16; i++) *(uint4*)(col + i*4) = make_uint4(0,0,0,0);
        }
    }
    CP_WAIT0();
    __syncthreads();
    float acc[8][4] = {};
    gemm_mma<132,136,16>(Ws, Xs, lane, mg, ng, acc);
    int nbase = ng*32 + (lane&3)*2;
    int ebase = mg*32 + (lane>>2);
#pragma unroll
    for (int mt = 0; mt < 2; mt++)
#pragma unroll
    for (int hf = 0; hf < 2; hf++) {
        int gr = rbase + ebase + mt*16 + hf*8;
        if (gr >= nrows) continue;
        int node = gr / nslots, slot = soff + gr % nslots;
        size_t ob = (size_t)node*576 + slot*64;
#pragma unroll
        for (int nt = 0; nt < 4; nt++) {
            int n = nbase + nt*8;
            float b0 = (slot == 0) ? bp[n] : 0.f, b1 = (slot == 0) ? bp[n+1] : 0.f;
            *(float2*)&g_x1[ob + n] = make_float2(
                x[ob + n]   + acc[mt*4+nt][hf*2+0] + b0,
                x[ob + n+1] + acc[mt*4+nt][hf*2+1] + b1);
        }
    }
}

__global__ void __launch_bounds__(256,2) ffn2_mma(
    const float* __restrict__ bf2, float* __restrict__ out)
{
    extern __shared__ uint32_t sm[];
    uint32_t* Xs = sm;
    uint32_t* Ws = sm + 16896;
    int deg, rbase, nslots, soff, nrows;
    node_row(blockIdx.x, &deg, &rbase, &nslots, &soff, &nrows);
    int t = threadIdx.x, lane = t & 31, w = t >> 5, mg = w & 3, ng = w >> 2;
    cp_chunk<2176,256>(Ws, g_Wf2c + deg*8704, t);
    {
        int r = t >> 1, h2 = t & 1;
        int gr = rbase + r;
        uint32_t* col = Xs + r*132 + h2*64;
        if (gr < nrows) {
            int node = gr / nslots, slot = soff + gr % nslots;
            const float4* hp = (slot == 0)
                ? (const float4*)&g_gsil[(size_t)node*128 + h2*64]
                : (const float4*)&g_h[(size_t)node*1024 + (size_t)(slot-1)*128 + h2*64];
#pragma unroll
            for (int i = 0; i < 16; i++) {
                float4 v = hp[i];
                *(uint4*)(col + i*4) = make_uint4(f2tf(v.x), f2tf(v.y), f2tf(v.z), f2tf(v.w));
            }
        } else {
#pragma unroll
            for (int i = 0; i < 16; i++) *(uint4*)(col + i*4) = make_uint4(0,0,0,0);
        }
    }
    CP_WAIT0();
    __syncthreads();
    float acc[8][4] = {};
    gemm_mma<132,136,16>(Ws, Xs, lane, mg, ng, acc);
    int nbase = ng*32 + (lane&3)*2;
    int ebase = mg*32 + (lane>>2);
#pragma unroll
    for (int mt = 0; mt < 2; mt++)
#pragma unroll
    for (int hf = 0; hf < 2; hf++) {
        int gr = rbase + ebase + mt*16 + hf*8;
        if (gr >= nrows) continue;
        int node = gr / nslots, slot = soff + gr % nslots;
        size_t ob = (size_t)node*576 + slot*64;
#pragma unroll
        for (int nt = 0; nt < 4; nt++) {
            int n = nbase + nt*8;
            float b0 = (slot == 0) ? bf2[n] : 0.f, b1 = (slot == 0) ? bf2[n+1] : 0.f;
            *(float2*)&out[ob + n] = make_float2(
                g_x1[ob + n]   + acc[mt*4+nt][hf*2+0] + b0,
                g_x1[ob + n+1] + acc[mt*4+nt][hf*2+1] + b1);
        }
    }
}

#define F_T1 469
#define F_GRID 1251
__global__ void __launch_bounds__(256) ffn1_mma()
{
    extern __shared__ uint32_t sm[];
    uint32_t* Xs = sm;            // 4352
    uint32_t* Ws = sm + 4352;     // 8448
    int b = blockIdx.x, deg, rbase, nslots, soff, nrows;
    if (b < F_T1) { deg=1; rbase=b*64;         nslots=3; soff=1; nrows=30000; }
    else          { deg=2; rbase=(b-F_T1)*64;  nslots=5; soff=4; nrows=50000; }
    int t = threadIdx.x, lane = t & 31, w = t >> 5, mg = w & 1, ng = w >> 1;
    cp_chunk<2112,256>(Ws, g_Wf1c + deg*8448, t);
    {
        int r = t >> 2, q = t & 3;
        int gr = rbase + r;
        uint32_t* col = Xs + r*68 + q*16;
        if (gr < nrows) {
            int node = gr / nslots, slot = soff + gr % nslots;
            const float4* yp = (const float4*)&g_yn[(size_t)node*576 + slot*64 + q*16];
#pragma unroll
            for (int i = 0; i < 4; i++) {
                float4 v = yp[i];
                *(uint4*)(col + i*4) = make_uint4(f2tf(v.x), f2tf(v.y), f2tf(v.z), f2tf(v.w));
            }
        } else {
#pragma unroll
            for (int i = 0; i < 4; i++) *(uint4*)(col + i*4) = make_uint4(0,0,0,0);
        }
    }
    CP_WAIT0();
    __syncthreads();
    float acc[8][4] = {};
    gemm_mma<68,264,8>(Ws, Xs, lane, mg, ng, acc);
    int nbase = ng*32 + (lane&3)*2;
    int ebase = mg*32 + (lane>>2);
#pragma unroll
    for (int mt = 0; mt < 2; mt++)
#pragma unroll
    for (int hf = 0; hf < 2; hf++) {
        int gr = rbase + ebase + mt*16 + hf*8;
        if (gr >= nrows) continue;
        int node = gr / nslots, slot = soff + gr % nslots;
        size_t hb = (size_t)node*1024 + (size_t)(slot-1)*128;
        size_t gsb = (size_t)node*128;
#pragma unroll
        for (int nt = 0; nt < 4; nt++) {
            int n = nbase + nt*8;
            float2 gs = *(const float2*)&g_gsig[gsb + n];
            *(float2*)&g_h[hb + n] = make_float2(
                acc[mt*4+nt][hf*2+0]*gs.x, acc[mt*4+nt][hf*2+1]*gs.y);
        }
    }
}

// ---------------- launch ----------------
extern "C" void kernel_launch(void* const* d_in, const int* in_sizes, int n_in,
                              void* d_out, int out_size)
{
    const float* x     = (const float*)d_in[0];
    const float* edist = (const float*)d_in[1];
    const float* rl    = (const float*)d_in[2];
    const float* semb  = (const float*)d_in[3];
    const float* temb  = (const float*)d_in[4];
    const float* W1    = (const float*)d_in[5];
    const float* b1    = (const float*)d_in[6];
    const float* W2    = (const float*)d_in[7];
    const float* b2    = (const float*)d_in[8];
    const float* Wc1   = (const float*)d_in[9];
    const float* Wm0   = (const float*)d_in[10];
    const float* lng   = (const float*)d_in[11];
    const float* lnb   = (const float*)d_in[12];
    const float* adot  = (const float*)d_in[13];
    const float* Wxj   = (const float*)d_in[14];
    const float* Wc2   = (const float*)d_in[15];
    const float* Wp    = (const float*)d_in[16];
    const float* bp    = (const float*)d_in[17];
    const float* Wg    = (const float*)d_in[18];
    const float* bg    = (const float*)d_in[19];
    const float* Wf1   = (const float*)d_in[20];
    const float* Wf2   = (const float*)d_in[22];
    const float* bf2   = (const float*)d_in[23];
    const int*   anum  = (const int*)d_in[24];
    const int*   eidx  = (const int*)d_in[25];
    float* out = (float*)d_out;

    float *p_xn, *p_x1, *p_yn;
    cudaGetSymbolAddress((void**)&p_xn, g_xn);
    cudaGetSymbolAddress((void**)&p_x1, g_x1);
    cudaGetSymbolAddress((void**)&p_yn, g_yn);

    static bool attr_set = false;
    if (!attr_set) {
        cudaFuncSetAttribute(rad_kernel,   cudaFuncAttributeMaxDynamicSharedMemorySize, 102400);
        cudaFuncSetAttribute(extra_kernel, cudaFuncAttributeMaxDynamicSharedMemorySize, 102400);
        cudaFuncSetAttribute(conv_kernel,  cudaFuncAttributeMaxDynamicSharedMemorySize, 211968);
        cudaFuncSetAttribute(proj_mma,     cudaFuncAttributeMaxDynamicSharedMemorySize, 102400);
        cudaFuncSetAttribute(ffn2_mma,     cudaFuncAttributeMaxDynamicSharedMemorySize, 102400);
        cudaFuncSetAttribute(ffn1_mma,     cudaFuncAttributeMaxDynamicSharedMemorySize, 51200);
        cudaFuncSetAttribute(xjp_mma,      cudaFuncAttributeMaxDynamicSharedMemorySize, 51200);
        cudaFuncSetAttribute(gate_mma,     cudaFuncAttributeMaxDynamicSharedMemorySize, 51200);
        attr_set = true;
    }

    wconv_kernel<<<(WCONV_N + 255)/256, 256>>>(W1, W2, Wm0, Wc1, Wc2, Wp, Wf1, Wf2, Wxj, Wg);
    zero_kernel<<<(NN*1152/4 + 255)/256, 256>>>();
    enorm_kernel<<<NN/4, 256>>>(x, p_xn);
    xjp_mma<<<XJ_GRID, 256, 51200>>>();
    rad_kernel<<<NE/128, 512, 102400>>>(edist, semb, temb, b1, b2, anum, eidx);
    extra_kernel<<<NE/128, 512, 102400>>>(lng, lnb, adot, eidx);
    conv_kernel<<<NE/128, 512, 211968>>>(rl, eidx);
    proj_mma<<<P_GRID, 256, 102400>>>(x, bp);
    enorm_kernel<<<NN/4, 256>>>(p_x1, p_yn);
    gate_mma<<<GATE_GRID, 256, 51200>>>(bg);
    ffn1_mma<<<F_GRID, 256, 51200>>>();
    ffn2_mma<<<P_GRID, 256, 102400>>>(bf2, out);
}